// round 3
// baseline (speedup 1.0000x reference)
#include <cuda_runtime.h>
#include <cuda_bf16.h>
#include <math.h>

#define NN 50000
#define NE 800000
#define NEL 850000   // edges + self loops
#define DF 128
#define DLIN 512
#define DOUT 4

// ---------------- device scratch (allocation-free, 16B aligned) ----------------
__device__ __align__(16) float g_x[NN * DF];
__device__ __align__(16) float g_h[NN * DF];
__device__ __align__(16) float g_agg[NN * DF];
__device__ __align__(16) float g_es[NN];
__device__ __align__(16) float g_ed[NN];
__device__ __align__(16) unsigned g_m[NN];
__device__ __align__(16) float g_denom[NN];
__device__ __align__(16) float g_e[NEL];
__device__ __align__(16) float g_ex[NEL];
__device__ __align__(16) int g_src[NEL];
__device__ __align__(16) int g_dst[NEL];
__device__ __align__(16) float g_y0[NN * DLIN];
__device__ __align__(16) float g_y1[NN * DLIN];
__device__ int g_is64;

// ---------------- helpers ----------------
__device__ __forceinline__ unsigned f2ord(float f) {
    unsigned u = __float_as_uint(f);
    return (u & 0x80000000u) ? ~u : (u | 0x80000000u);
}
__device__ __forceinline__ float ord2f(unsigned u) {
    return (u & 0x80000000u) ? __uint_as_float(u & 0x7fffffffu) : __uint_as_float(~u);
}
__device__ __forceinline__ float leaky(float v) { return v > 0.f ? v : 0.2f * v; }

// ---------------- edge dtype probe ----------------
// If buffer is int64 (values < 2^31), int32 view is [v,0,v,0,...]: odd slots all 0.
// Reads only the first 512 int32 = 2KB, safe for either dtype.
__global__ void k_detect_dtype(const int* __restrict__ ei32) {
    if (threadIdx.x != 0 || blockIdx.x != 0) return;
    int zeros = 0;
    for (int i = 0; i < 256; i++)
        if (ei32[2 * i + 1] == 0) zeros++;
    g_is64 = (zeros >= 250) ? 1 : 0;
}

// ---------------- edge list build (int32 or int64 source, append self loops) ----------------
__global__ void k_build_edges(const void* __restrict__ ei) {
    int i = blockIdx.x * blockDim.x + threadIdx.x;
    if (i >= NEL) return;
    int s, d;
    if (i < NE) {
        if (g_is64) {
            const long long* p = (const long long*)ei;
            s = (int)p[i];
            d = (int)p[NE + i];
        } else {
            const int* p = (const int*)ei;
            s = p[i];
            d = p[NE + i];
        }
        // defensive clamp: no downstream kernel can fault on a bad index
        s = min(max(s, 0), NN - 1);
        d = min(max(d, 0), NN - 1);
    } else {
        s = i - NE;
        d = i - NE;
    }
    g_src[i] = s;
    g_dst[i] = d;
}

// ---------------- SGEMM: C[M,N] = A[M,K] @ B[K,N] (+bias)(+relu) ----------------
__global__ void k_sgemm(const float* __restrict__ A, const float* __restrict__ B,
                        const float* __restrict__ bias, float* __restrict__ C,
                        int M, int N, int K, int act) {
    const int BM = 64, BN = 64, BK = 16, TM = 4, TN = 4;
    __shared__ float As[BK][BM];
    __shared__ float Bs[BK][BN];

    int tid = threadIdx.x;
    int rowBase = blockIdx.y * BM;
    int colBase = blockIdx.x * BN;

    int aRow = tid >> 2;
    int aCol = (tid & 3) << 2;
    int bRow = tid >> 4;
    int bCol = (tid & 15) << 2;

    int ty = tid >> 4;
    int tx = tid & 15;

    float acc[TM][TN];
#pragma unroll
    for (int i = 0; i < TM; i++)
#pragma unroll
        for (int j = 0; j < TN; j++) acc[i][j] = 0.f;

    int aGlobRow = rowBase + aRow;
    if (aGlobRow >= M) aGlobRow = M - 1;   // clamped load, store guarded

    for (int k0 = 0; k0 < K; k0 += BK) {
        float4 av = *(const float4*)(A + (size_t)aGlobRow * K + k0 + aCol);
        As[aCol + 0][aRow] = av.x;
        As[aCol + 1][aRow] = av.y;
        As[aCol + 2][aRow] = av.z;
        As[aCol + 3][aRow] = av.w;
        float4 bv = *(const float4*)(B + (size_t)(k0 + bRow) * N + colBase + bCol);
        *(float4*)&Bs[bRow][bCol] = bv;
        __syncthreads();
#pragma unroll
        for (int k = 0; k < BK; k++) {
            float ra[TM], rb[TN];
#pragma unroll
            for (int i = 0; i < TM; i++) ra[i] = As[k][ty * TM + i];
#pragma unroll
            for (int j = 0; j < TN; j++) rb[j] = Bs[k][tx * TN + j];
#pragma unroll
            for (int i = 0; i < TM; i++)
#pragma unroll
                for (int j = 0; j < TN; j++) acc[i][j] += ra[i] * rb[j];
        }
        __syncthreads();
    }

#pragma unroll
    for (int i = 0; i < TM; i++) {
        int r = rowBase + ty * TM + i;
        if (r >= M) continue;
#pragma unroll
        for (int j = 0; j < TN; j++) {
            int c = colBase + tx * TN + j;
            float v = acc[i][j];
            if (bias) v += bias[c];
            if (act == 1) v = fmaxf(v, 0.f);
            C[(size_t)r * N + c] = v;
        }
    }
}

// ---------------- per-node attention scalars ----------------
__global__ void k_es_ed(const float* __restrict__ a_src, const float* __restrict__ a_dst) {
    int n = blockIdx.x * (blockDim.x >> 5) + (threadIdx.x >> 5);
    int lane = threadIdx.x & 31;
    if (n >= NN) return;
    float4 hv = *(const float4*)(g_h + (size_t)n * DF + lane * 4);
    float4 as = *(const float4*)(a_src + lane * 4);
    float4 ad = *(const float4*)(a_dst + lane * 4);
    float s = hv.x * as.x + hv.y * as.y + hv.z * as.z + hv.w * as.w;
    float d = hv.x * ad.x + hv.y * ad.y + hv.z * ad.z + hv.w * ad.w;
#pragma unroll
    for (int o = 16; o > 0; o >>= 1) {
        s += __shfl_xor_sync(0xffffffff, s, o);
        d += __shfl_xor_sync(0xffffffff, d, o);
    }
    if (lane == 0) {
        g_es[n] = s;
        g_ed[n] = d;
    }
}

__global__ void k_init_seg() {
    int n = blockIdx.x * blockDim.x + threadIdx.x;
    if (n >= NN) return;
    g_m[n] = 0u;
    g_denom[n] = 0.f;
}

__global__ void k_edge_max() {
    int e = blockIdx.x * blockDim.x + threadIdx.x;
    if (e >= NEL) return;
    int s = g_src[e], d = g_dst[e];
    float v = leaky(g_es[s] + g_ed[d]);
    g_e[e] = v;
    atomicMax(&g_m[d], f2ord(v));
}

__global__ void k_edge_exp() {
    int e = blockIdx.x * blockDim.x + threadIdx.x;
    if (e >= NEL) return;
    int d = g_dst[e];
    float v = expf(g_e[e] - ord2f(g_m[d]));
    g_ex[e] = v;
    atomicAdd(&g_denom[d], v);
}

// warp per edge: agg[dst] += alpha * h[src]
__global__ void k_edge_aggr() {
    int w = (blockIdx.x * blockDim.x + threadIdx.x) >> 5;
    int lane = threadIdx.x & 31;
    if (w >= NEL) return;
    int s = g_src[w], d = g_dst[w];
    float alpha = g_ex[w] / g_denom[d];
    float4 hv = *(const float4*)(g_h + (size_t)s * DF + lane * 4);
    float* outp = g_agg + (size_t)d * DF + lane * 4;
    float a = alpha * hv.x, b = alpha * hv.y, c = alpha * hv.z, e = alpha * hv.w;
    asm volatile("red.global.add.v4.f32 [%0], {%1,%2,%3,%4};"
                 :: "l"(outp), "f"(a), "f"(b), "f"(c), "f"(e) : "memory");
}

__global__ void k_finish_layer(const float* __restrict__ b) {
    int i = blockIdx.x * blockDim.x + threadIdx.x;
    if (i >= NN * DF) return;
    int j = i & (DF - 1);
    g_x[i] = leaky(g_agg[i] + b[j]);
}

__global__ void k_out(const float* __restrict__ Y, const float* __restrict__ Wout,
                      const float* __restrict__ bout, float* __restrict__ out) {
    int n = blockIdx.x * (blockDim.x >> 5) + (threadIdx.x >> 5);
    int lane = threadIdx.x & 31;
    if (n >= NN) return;
    float acc0 = 0.f, acc1 = 0.f, acc2 = 0.f, acc3 = 0.f;
    const float* y = Y + (size_t)n * DLIN;
    for (int k = lane; k < DLIN; k += 32) {
        float v = y[k];
        const float4 wv = *(const float4*)(Wout + k * 4);
        acc0 += v * wv.x;
        acc1 += v * wv.y;
        acc2 += v * wv.z;
        acc3 += v * wv.w;
    }
#pragma unroll
    for (int o = 16; o > 0; o >>= 1) {
        acc0 += __shfl_xor_sync(0xffffffff, acc0, o);
        acc1 += __shfl_xor_sync(0xffffffff, acc1, o);
        acc2 += __shfl_xor_sync(0xffffffff, acc2, o);
        acc3 += __shfl_xor_sync(0xffffffff, acc3, o);
    }
    if (lane == 0) {
        float4 r;
        r.x = acc0 + bout[0];
        r.y = acc1 + bout[1];
        r.z = acc2 + bout[2];
        r.w = acc3 + bout[3];
        *(float4*)(out + (size_t)n * 4) = r;
    }
}

extern "C" void kernel_launch(void* const* d_in, const int* in_sizes, int n_in,
                              void* d_out, int out_size) {
    const float *x, *conv_W, *conv_as, *conv_ad, *conv_b;
    const float *lin_W0, *lin_b0, *lin_W1, *lin_b1, *lin_W2, *lin_b2, *lin_Wout, *lin_bout;
    const void* ei;

    if (in_sizes[0] == NN * DF) {
        // dict (insertion) order
        x        = (const float*)d_in[0];
        ei       = d_in[1];
        conv_W   = (const float*)d_in[2];
        conv_as  = (const float*)d_in[3];
        conv_ad  = (const float*)d_in[4];
        conv_b   = (const float*)d_in[5];
        lin_W0   = (const float*)d_in[6];
        lin_b0   = (const float*)d_in[7];
        lin_W1   = (const float*)d_in[8];
        lin_b1   = (const float*)d_in[9];
        lin_W2   = (const float*)d_in[10];
        lin_b2   = (const float*)d_in[11];
        lin_Wout = (const float*)d_in[12];
        lin_bout = (const float*)d_in[13];
    } else {
        // alphabetical order
        conv_W   = (const float*)d_in[0];
        conv_ad  = (const float*)d_in[1];
        conv_as  = (const float*)d_in[2];
        conv_b   = (const float*)d_in[3];
        ei       = d_in[4];
        lin_W0   = (const float*)d_in[5];
        lin_W1   = (const float*)d_in[6];
        lin_W2   = (const float*)d_in[7];
        lin_Wout = (const float*)d_in[8];
        lin_b0   = (const float*)d_in[9];
        lin_b1   = (const float*)d_in[10];
        lin_b2   = (const float*)d_in[11];
        lin_bout = (const float*)d_in[12];
        x        = (const float*)d_in[13];
    }
    float* out = (float*)d_out;

    void *p_x, *p_h, *p_agg, *p_y0, *p_y1;
    cudaGetSymbolAddress(&p_x, g_x);
    cudaGetSymbolAddress(&p_h, g_h);
    cudaGetSymbolAddress(&p_agg, g_agg);
    cudaGetSymbolAddress(&p_y0, g_y0);
    cudaGetSymbolAddress(&p_y1, g_y1);

    k_detect_dtype<<<1, 32>>>((const int*)ei);
    k_build_edges<<<(NEL + 255) / 256, 256>>>(ei);

    dim3 gemmGrid128(DF / 64, (NN + 63) / 64);
    const int warpsPerBlock = 8;

    const float* curX = x;
    for (int layer = 0; layer < 3; layer++) {
        const float* W  = conv_W + (size_t)layer * DF * DF;
        const float* as = conv_as + (size_t)layer * DF;
        const float* ad = conv_ad + (size_t)layer * DF;
        const float* b  = conv_b + (size_t)layer * DF;

        k_sgemm<<<gemmGrid128, 256>>>(curX, W, nullptr, (float*)p_h, NN, DF, DF, 0);
        k_es_ed<<<(NN + warpsPerBlock - 1) / warpsPerBlock, warpsPerBlock * 32>>>(as, ad);
        k_init_seg<<<(NN + 255) / 256, 256>>>();
        cudaMemsetAsync(p_agg, 0, (size_t)NN * DF * sizeof(float));
        k_edge_max<<<(NEL + 255) / 256, 256>>>();
        k_edge_exp<<<(NEL + 255) / 256, 256>>>();
        k_edge_aggr<<<(NEL * 32 + 255) / 256, 256>>>();
        k_finish_layer<<<(NN * DF + 255) / 256, 256>>>(b);
        curX = (const float*)p_x;
    }

    dim3 gemmGrid512(DLIN / 64, (NN + 63) / 64);
    k_sgemm<<<gemmGrid512, 256>>>((const float*)p_x, lin_W0, lin_b0, (float*)p_y0, NN, DLIN, DF, 1);
    k_sgemm<<<gemmGrid512, 256>>>((const float*)p_y0, lin_W1, lin_b1, (float*)p_y1, NN, DLIN, DLIN, 1);
    k_sgemm<<<gemmGrid512, 256>>>((const float*)p_y1, lin_W2, lin_b2, (float*)p_y0, NN, DLIN, DLIN, 1);
    k_out<<<(NN + warpsPerBlock - 1) / warpsPerBlock, warpsPerBlock * 32>>>(
        (const float*)p_y0, lin_Wout, lin_bout, out);
}

// round 6
// speedup vs baseline: 1.4144x; 1.4144x over previous
#include <cuda_runtime.h>
#include <cuda_bf16.h>
#include <math.h>

#define NN 50000
#define NE 800000
#define NEL 850000
#define DF 128
#define DLIN 512
#define DOUT 4

// ---------------- device scratch ----------------
__device__ __align__(16) float g_x[NN * DF];
__device__ __align__(16) float g_h[NN * DF];
__device__ __align__(16) float g_agg[NN * DF];
__device__ __align__(16) float g_es[NN];
__device__ __align__(16) float g_ed[NN];
__device__ __align__(16) unsigned g_m[NN];
__device__ __align__(16) float g_denom[NN];
__device__ __align__(16) float g_e[NEL];
__device__ __align__(16) float g_ex[NEL];
__device__ __align__(16) int g_src[NEL];
__device__ __align__(16) int g_dst[NEL];
__device__ __align__(16) float g_y0[NN * DLIN];
__device__ __align__(16) float g_y1[NN * DLIN];
__device__ int g_is64;

// ---------------- helpers ----------------
__device__ __forceinline__ unsigned f2ord(float f) {
    unsigned u = __float_as_uint(f);
    return (u & 0x80000000u) ? ~u : (u | 0x80000000u);
}
__device__ __forceinline__ float ord2f(unsigned u) {
    return (u & 0x80000000u) ? __uint_as_float(u & 0x7fffffffu) : __uint_as_float(~u);
}
__device__ __forceinline__ float leaky(float v) { return v > 0.f ? v : 0.2f * v; }
__device__ __forceinline__ float to_tf32(float f) {
    float r;
    asm("cvt.rna.tf32.f32 %0, %1;" : "=f"(r) : "f"(f));
    return r;
}

// ---------------- edge dtype probe ----------------
__global__ void k_detect_dtype(const int* __restrict__ ei32) {
    if (threadIdx.x != 0 || blockIdx.x != 0) return;
    int zeros = 0;
    for (int i = 0; i < 256; i++)
        if (ei32[2 * i + 1] == 0) zeros++;
    g_is64 = (zeros >= 250) ? 1 : 0;
}

__global__ void k_build_edges(const void* __restrict__ ei) {
    int i = blockIdx.x * blockDim.x + threadIdx.x;
    if (i >= NEL) return;
    int s, d;
    if (i < NE) {
        if (g_is64) {
            const long long* p = (const long long*)ei;
            s = (int)p[i];
            d = (int)p[NE + i];
        } else {
            const int* p = (const int*)ei;
            s = p[i];
            d = p[NE + i];
        }
        s = min(max(s, 0), NN - 1);
        d = min(max(d, 0), NN - 1);
    } else {
        s = i - NE;
        d = i - NE;
    }
    g_src[i] = s;
    g_dst[i] = d;
}

// ---------------- split-TF32 tensor-core GEMM (fp32 accuracy) ----------------
// C[M,N] = A[M,K] @ B[K,N] (+bias)(+relu). BM=128 BN=128 BK=32.
// 256 threads = 8 warps as 2(m) x 4(n); warp tile 64x32; mma.m16n8k8.
// Each fp32 value split into tf32 hi + tf32 lo at fragment-load time;
// acc += Ahi*Bhi + Ahi*Blo + Alo*Bhi  (~22 mantissa bits).
#define AS_STRIDE 36
#define BS_STRIDE 136

#define MMA_TF32(ACC, A0, A1, A2, A3, B0, B1)                                   \
    asm volatile(                                                                \
        "mma.sync.aligned.m16n8k8.row.col.f32.tf32.tf32.f32 "                    \
        "{%0,%1,%2,%3}, {%4,%5,%6,%7}, {%8,%9}, {%0,%1,%2,%3};"                  \
        : "+f"((ACC)[0]), "+f"((ACC)[1]), "+f"((ACC)[2]), "+f"((ACC)[3])         \
        : "r"(__float_as_uint(A0)), "r"(__float_as_uint(A1)),                    \
          "r"(__float_as_uint(A2)), "r"(__float_as_uint(A3)),                    \
          "r"(__float_as_uint(B0)), "r"(__float_as_uint(B1)))

__global__ __launch_bounds__(256, 2) void k_mma(
    const float* __restrict__ A, const float* __restrict__ B,
    const float* __restrict__ bias, float* __restrict__ C,
    int M, int N, int K, int act) {
    __shared__ float As[128][AS_STRIDE];   // [m][k] raw fp32
    __shared__ float Bs[32][BS_STRIDE];    // [k][n] raw fp32

    const int tid = threadIdx.x;
    const int wid = tid >> 5;
    const int lane = tid & 31;
    const int warpM = wid >> 2;
    const int warpN = wid & 3;
    const int rowBase = blockIdx.y * 128;
    const int colBase = blockIdx.x * 128;

    const int lq = lane >> 2;
    const int lr = lane & 3;

    float acc[4][4][4];
#pragma unroll
    for (int i = 0; i < 4; i++)
#pragma unroll
        for (int j = 0; j < 4; j++)
#pragma unroll
            for (int r = 0; r < 4; r++) acc[i][j][r] = 0.f;

    const int aRow0 = tid >> 3;
    const int aCol4 = (tid & 7) << 2;
    const int bRow0 = tid >> 5;
    const int bCol4 = (tid & 31) << 2;

    for (int k0 = 0; k0 < K; k0 += 32) {
#pragma unroll
        for (int i = 0; i < 4; i++) {
            int r = aRow0 + i * 32;
            int gr = rowBase + r;
            if (gr >= M) gr = M - 1;
            float4 v = *(const float4*)(A + (size_t)gr * K + k0 + aCol4);
            As[r][aCol4 + 0] = v.x;
            As[r][aCol4 + 1] = v.y;
            As[r][aCol4 + 2] = v.z;
            As[r][aCol4 + 3] = v.w;
        }
#pragma unroll
        for (int i = 0; i < 4; i++) {
            int r = bRow0 + i * 8;
            float4 v = *(const float4*)(B + (size_t)(k0 + r) * N + colBase + bCol4);
            Bs[r][bCol4 + 0] = v.x;
            Bs[r][bCol4 + 1] = v.y;
            Bs[r][bCol4 + 2] = v.z;
            Bs[r][bCol4 + 3] = v.w;
        }
        __syncthreads();

#pragma unroll
        for (int kk = 0; kk < 4; kk++) {
            const int kb = kk * 8;
            // B fragments: hi + lo
            float bhi[4][2], blo[4][2];
#pragma unroll
            for (int nt = 0; nt < 4; nt++) {
                int c = warpN * 32 + nt * 8 + lq;
                float b0 = Bs[kb + lr][c];
                float b1 = Bs[kb + lr + 4][c];
                bhi[nt][0] = to_tf32(b0);
                blo[nt][0] = to_tf32(b0 - bhi[nt][0]);
                bhi[nt][1] = to_tf32(b1);
                blo[nt][1] = to_tf32(b1 - bhi[nt][1]);
            }
#pragma unroll
            for (int mt = 0; mt < 4; mt++) {
                int r = warpM * 64 + mt * 16 + lq;
                float a0 = As[r][kb + lr];
                float a1 = As[r + 8][kb + lr];
                float a2 = As[r][kb + lr + 4];
                float a3 = As[r + 8][kb + lr + 4];
                float ah0 = to_tf32(a0), al0 = to_tf32(a0 - ah0);
                float ah1 = to_tf32(a1), al1 = to_tf32(a1 - ah1);
                float ah2 = to_tf32(a2), al2 = to_tf32(a2 - ah2);
                float ah3 = to_tf32(a3), al3 = to_tf32(a3 - ah3);
#pragma unroll
                for (int nt = 0; nt < 4; nt++) {
                    MMA_TF32(acc[mt][nt], al0, al1, al2, al3, bhi[nt][0], bhi[nt][1]);
                    MMA_TF32(acc[mt][nt], ah0, ah1, ah2, ah3, blo[nt][0], blo[nt][1]);
                    MMA_TF32(acc[mt][nt], ah0, ah1, ah2, ah3, bhi[nt][0], bhi[nt][1]);
                }
            }
        }
        __syncthreads();
    }

#pragma unroll
    for (int mt = 0; mt < 4; mt++) {
        int r0 = rowBase + warpM * 64 + mt * 16 + lq;
#pragma unroll
        for (int nt = 0; nt < 4; nt++) {
            int c = colBase + warpN * 32 + nt * 8 + lr * 2;
            float b0 = bias ? bias[c] : 0.f;
            float b1 = bias ? bias[c + 1] : 0.f;
            if (r0 < M) {
                float v0 = acc[mt][nt][0] + b0;
                float v1 = acc[mt][nt][1] + b1;
                if (act) { v0 = fmaxf(v0, 0.f); v1 = fmaxf(v1, 0.f); }
                *(float2*)(C + (size_t)r0 * N + c) = make_float2(v0, v1);
            }
            if (r0 + 8 < M) {
                float v2 = acc[mt][nt][2] + b0;
                float v3 = acc[mt][nt][3] + b1;
                if (act) { v2 = fmaxf(v2, 0.f); v3 = fmaxf(v3, 0.f); }
                *(float2*)(C + (size_t)(r0 + 8) * N + c) = make_float2(v2, v3);
            }
        }
    }
}

// ---------------- per-node attention scalars ----------------
__global__ void k_es_ed(const float* __restrict__ a_src, const float* __restrict__ a_dst) {
    int n = blockIdx.x * (blockDim.x >> 5) + (threadIdx.x >> 5);
    int lane = threadIdx.x & 31;
    if (n >= NN) return;
    float4 hv = *(const float4*)(g_h + (size_t)n * DF + lane * 4);
    float4 as = *(const float4*)(a_src + lane * 4);
    float4 ad = *(const float4*)(a_dst + lane * 4);
    float s = hv.x * as.x + hv.y * as.y + hv.z * as.z + hv.w * as.w;
    float d = hv.x * ad.x + hv.y * ad.y + hv.z * ad.z + hv.w * ad.w;
#pragma unroll
    for (int o = 16; o > 0; o >>= 1) {
        s += __shfl_xor_sync(0xffffffff, s, o);
        d += __shfl_xor_sync(0xffffffff, d, o);
    }
    if (lane == 0) {
        g_es[n] = s;
        g_ed[n] = d;
    }
}

__global__ void k_init_seg() {
    int n = blockIdx.x * blockDim.x + threadIdx.x;
    if (n >= NN) return;
    g_m[n] = 0u;
    g_denom[n] = 0.f;
}

__global__ void k_edge_max() {
    int e = blockIdx.x * blockDim.x + threadIdx.x;
    if (e >= NEL) return;
    int s = g_src[e], d = g_dst[e];
    float v = leaky(g_es[s] + g_ed[d]);
    g_e[e] = v;
    atomicMax(&g_m[d], f2ord(v));
}

__global__ void k_edge_exp() {
    int e = blockIdx.x * blockDim.x + threadIdx.x;
    if (e >= NEL) return;
    int d = g_dst[e];
    float v = expf(g_e[e] - ord2f(g_m[d]));
    g_ex[e] = v;
    atomicAdd(&g_denom[d], v);
}

__global__ void k_edge_aggr() {
    int w = (blockIdx.x * blockDim.x + threadIdx.x) >> 5;
    int lane = threadIdx.x & 31;
    if (w >= NEL) return;
    int s = g_src[w], d = g_dst[w];
    float alpha = g_ex[w] / g_denom[d];
    float4 hv = *(const float4*)(g_h + (size_t)s * DF + lane * 4);
    float* outp = g_agg + (size_t)d * DF + lane * 4;
    float a = alpha * hv.x, b = alpha * hv.y, c = alpha * hv.z, e = alpha * hv.w;
    asm volatile("red.global.add.v4.f32 [%0], {%1,%2,%3,%4};"
                 :: "l"(outp), "f"(a), "f"(b), "f"(c), "f"(e) : "memory");
}

__global__ void k_finish_layer(const float* __restrict__ b) {
    int i = blockIdx.x * blockDim.x + threadIdx.x;
    if (i >= NN * DF) return;
    int j = i & (DF - 1);
    g_x[i] = leaky(g_agg[i] + b[j]);
}

__global__ void k_out(const float* __restrict__ Y, const float* __restrict__ Wout,
                      const float* __restrict__ bout, float* __restrict__ out) {
    int n = blockIdx.x * (blockDim.x >> 5) + (threadIdx.x >> 5);
    int lane = threadIdx.x & 31;
    if (n >= NN) return;
    float acc0 = 0.f, acc1 = 0.f, acc2 = 0.f, acc3 = 0.f;
    const float* y = Y + (size_t)n * DLIN;
    for (int k = lane; k < DLIN; k += 32) {
        float v = y[k];
        const float4 wv = *(const float4*)(Wout + k * 4);
        acc0 += v * wv.x;
        acc1 += v * wv.y;
        acc2 += v * wv.z;
        acc3 += v * wv.w;
    }
#pragma unroll
    for (int o = 16; o > 0; o >>= 1) {
        acc0 += __shfl_xor_sync(0xffffffff, acc0, o);
        acc1 += __shfl_xor_sync(0xffffffff, acc1, o);
        acc2 += __shfl_xor_sync(0xffffffff, acc2, o);
        acc3 += __shfl_xor_sync(0xffffffff, acc3, o);
    }
    if (lane == 0) {
        float4 r;
        r.x = acc0 + bout[0];
        r.y = acc1 + bout[1];
        r.z = acc2 + bout[2];
        r.w = acc3 + bout[3];
        *(float4*)(out + (size_t)n * 4) = r;
    }
}

extern "C" void kernel_launch(void* const* d_in, const int* in_sizes, int n_in,
                              void* d_out, int out_size) {
    const float *x, *conv_W, *conv_as, *conv_ad, *conv_b;
    const float *lin_W0, *lin_b0, *lin_W1, *lin_b1, *lin_W2, *lin_b2, *lin_Wout, *lin_bout;
    const void* ei;

    if (in_sizes[0] == NN * DF) {
        x        = (const float*)d_in[0];
        ei       = d_in[1];
        conv_W   = (const float*)d_in[2];
        conv_as  = (const float*)d_in[3];
        conv_ad  = (const float*)d_in[4];
        conv_b   = (const float*)d_in[5];
        lin_W0   = (const float*)d_in[6];
        lin_b0   = (const float*)d_in[7];
        lin_W1   = (const float*)d_in[8];
        lin_b1   = (const float*)d_in[9];
        lin_W2   = (const float*)d_in[10];
        lin_b2   = (const float*)d_in[11];
        lin_Wout = (const float*)d_in[12];
        lin_bout = (const float*)d_in[13];
    } else {
        conv_W   = (const float*)d_in[0];
        conv_ad  = (const float*)d_in[1];
        conv_as  = (const float*)d_in[2];
        conv_b   = (const float*)d_in[3];
        ei       = d_in[4];
        lin_W0   = (const float*)d_in[5];
        lin_W1   = (const float*)d_in[6];
        lin_W2   = (const float*)d_in[7];
        lin_Wout = (const float*)d_in[8];
        lin_b0   = (const float*)d_in[9];
        lin_b1   = (const float*)d_in[10];
        lin_b2   = (const float*)d_in[11];
        lin_bout = (const float*)d_in[12];
        x        = (const float*)d_in[13];
    }
    float* out = (float*)d_out;

    void *p_x, *p_h, *p_agg, *p_y0, *p_y1;
    cudaGetSymbolAddress(&p_x, g_x);
    cudaGetSymbolAddress(&p_h, g_h);
    cudaGetSymbolAddress(&p_agg, g_agg);
    cudaGetSymbolAddress(&p_y0, g_y0);
    cudaGetSymbolAddress(&p_y1, g_y1);

    k_detect_dtype<<<1, 32>>>((const int*)ei);
    k_build_edges<<<(NEL + 255) / 256, 256>>>(ei);

    dim3 grid128(1, (NN + 127) / 128);
    dim3 grid512(DLIN / 128, (NN + 127) / 128);
    const int warpsPerBlock = 8;

    const float* curX = x;
    for (int layer = 0; layer < 3; layer++) {
        const float* W  = conv_W + (size_t)layer * DF * DF;
        const float* as = conv_as + (size_t)layer * DF;
        const float* ad = conv_ad + (size_t)layer * DF;
        const float* b  = conv_b + (size_t)layer * DF;

        k_mma<<<grid128, 256>>>(curX, W, nullptr, (float*)p_h, NN, DF, DF, 0);
        k_es_ed<<<(NN + warpsPerBlock - 1) / warpsPerBlock, warpsPerBlock * 32>>>(as, ad);
        k_init_seg<<<(NN + 255) / 256, 256>>>();
        cudaMemsetAsync(p_agg, 0, (size_t)NN * DF * sizeof(float));
        k_edge_max<<<(NEL + 255) / 256, 256>>>();
        k_edge_exp<<<(NEL + 255) / 256, 256>>>();
        k_edge_aggr<<<(NEL * 32 + 255) / 256, 256>>>();
        k_finish_layer<<<(NN * DF + 255) / 256, 256>>>(b);
        curX = (const float*)p_x;
    }

    k_mma<<<grid512, 256>>>((const float*)p_x, lin_W0, lin_b0, (float*)p_y0, NN, DLIN, DF, 1);
    k_mma<<<grid512, 256>>>((const float*)p_y0, lin_W1, lin_b1, (float*)p_y1, NN, DLIN, DLIN, 1);
    k_mma<<<grid512, 256>>>((const float*)p_y1, lin_W2, lin_b2, (float*)p_y0, NN, DLIN, DLIN, 1);
    k_out<<<(NN + warpsPerBlock - 1) / warpsPerBlock, warpsPerBlock * 32>>>(
        (const float*)p_y0, lin_Wout, lin_bout, out);
}

// round 7
// speedup vs baseline: 1.6748x; 1.1841x over previous
#include <cuda_runtime.h>
#include <cuda_bf16.h>
#include <math.h>

#define NN 50000
#define NE 800000
#define NEL 850000
#define DF 128
#define DLIN 512
#define DOUT 4
#define NBLK 49   // ceil(NN/1024)

// ---------------- device scratch ----------------
__device__ __align__(16) float g_x[NN * DF];
__device__ __align__(16) float g_h[NN * DF];
__device__ __align__(16) float g_es[NN];
__device__ __align__(16) float g_ed[NN];
__device__ __align__(16) int g_src[NEL];
__device__ __align__(16) int g_dst[NEL];
__device__ __align__(16) float g_y0[NN * DLIN];
__device__ __align__(16) float g_y1[NN * DLIN];
// CSR
__device__ __align__(16) int g_deg[NN];
__device__ __align__(16) int g_incl[NN];
__device__ __align__(16) int g_bsum[NBLK];
__device__ __align__(16) int g_boff[NBLK];
__device__ __align__(16) int g_rowstart[NN + 1];
__device__ __align__(16) int g_cursor[NN];
__device__ __align__(16) int g_csr[NEL];
__device__ int g_is64;

// ---------------- helpers ----------------
__device__ __forceinline__ float leaky(float v) { return v > 0.f ? v : 0.2f * v; }
__device__ __forceinline__ float to_tf32(float f) {
    float r;
    asm("cvt.rna.tf32.f32 %0, %1;" : "=f"(r) : "f"(f));
    return r;
}

// ---------------- edge dtype probe ----------------
__global__ void k_detect_dtype(const int* __restrict__ ei32) {
    if (threadIdx.x != 0 || blockIdx.x != 0) return;
    int zeros = 0;
    for (int i = 0; i < 256; i++)
        if (ei32[2 * i + 1] == 0) zeros++;
    g_is64 = (zeros >= 250) ? 1 : 0;
}

__global__ void k_build_edges(const void* __restrict__ ei) {
    int i = blockIdx.x * blockDim.x + threadIdx.x;
    if (i >= NEL) return;
    int s, d;
    if (i < NE) {
        if (g_is64) {
            const long long* p = (const long long*)ei;
            s = (int)p[i];
            d = (int)p[NE + i];
        } else {
            const int* p = (const int*)ei;
            s = p[i];
            d = p[NE + i];
        }
        s = min(max(s, 0), NN - 1);
        d = min(max(d, 0), NN - 1);
    } else {
        s = i - NE;
        d = i - NE;
    }
    g_src[i] = s;
    g_dst[i] = d;
}

// ---------------- CSR build ----------------
__global__ void k_zero_deg() {
    int i = blockIdx.x * blockDim.x + threadIdx.x;
    if (i < NN) g_deg[i] = 0;
}
__global__ void k_hist() {
    int e = blockIdx.x * blockDim.x + threadIdx.x;
    if (e >= NEL) return;
    atomicAdd(&g_deg[g_dst[e]], 1);
}
__global__ void k_scan1() {
    __shared__ int sm[1024];
    int i = blockIdx.x * 1024 + threadIdx.x;
    int v = (i < NN) ? g_deg[i] : 0;
    sm[threadIdx.x] = v;
    __syncthreads();
    for (int off = 1; off < 1024; off <<= 1) {
        int t = (threadIdx.x >= off) ? sm[threadIdx.x - off] : 0;
        __syncthreads();
        sm[threadIdx.x] += t;
        __syncthreads();
    }
    if (i < NN) g_incl[i] = sm[threadIdx.x];
    if (threadIdx.x == 1023) g_bsum[blockIdx.x] = sm[1023];
}
__global__ void k_scan2() {
    if (threadIdx.x == 0 && blockIdx.x == 0) {
        int run = 0;
        for (int b = 0; b < NBLK; b++) {
            int t = g_bsum[b];
            g_boff[b] = run;
            run += t;
        }
    }
}
__global__ void k_scan3() {
    int i = blockIdx.x * blockDim.x + threadIdx.x;
    if (i < NN) {
        int rs = g_incl[i] - g_deg[i] + g_boff[i >> 10];
        g_rowstart[i] = rs;
        g_cursor[i] = rs;
    }
    if (i == 0) g_rowstart[NN] = NEL;
}
__global__ void k_scatter() {
    int e = blockIdx.x * blockDim.x + threadIdx.x;
    if (e >= NEL) return;
    int pos = atomicAdd(&g_cursor[g_dst[e]], 1);
    g_csr[pos] = g_src[e];
}

// ---------------- split-TF32 tensor-core GEMM ----------------
#define AS_STRIDE 36
#define BS_STRIDE 136

#define MMA_TF32(ACC, A0, A1, A2, A3, B0, B1)                                   \
    asm volatile(                                                                \
        "mma.sync.aligned.m16n8k8.row.col.f32.tf32.tf32.f32 "                    \
        "{%0,%1,%2,%3}, {%4,%5,%6,%7}, {%8,%9}, {%0,%1,%2,%3};"                  \
        : "+f"((ACC)[0]), "+f"((ACC)[1]), "+f"((ACC)[2]), "+f"((ACC)[3])         \
        : "r"(__float_as_uint(A0)), "r"(__float_as_uint(A1)),                    \
          "r"(__float_as_uint(A2)), "r"(__float_as_uint(A3)),                    \
          "r"(__float_as_uint(B0)), "r"(__float_as_uint(B1)))

__global__ __launch_bounds__(256, 2) void k_mma(
    const float* __restrict__ A, const float* __restrict__ B,
    const float* __restrict__ bias, float* __restrict__ C,
    int M, int N, int K, int act) {
    __shared__ float As[128][AS_STRIDE];
    __shared__ float Bs[32][BS_STRIDE];

    const int tid = threadIdx.x;
    const int wid = tid >> 5;
    const int lane = tid & 31;
    const int warpM = wid >> 2;
    const int warpN = wid & 3;
    const int rowBase = blockIdx.y * 128;
    const int colBase = blockIdx.x * 128;

    const int lq = lane >> 2;
    const int lr = lane & 3;

    float acc[4][4][4];
#pragma unroll
    for (int i = 0; i < 4; i++)
#pragma unroll
        for (int j = 0; j < 4; j++)
#pragma unroll
            for (int r = 0; r < 4; r++) acc[i][j][r] = 0.f;

    const int aRow0 = tid >> 3;
    const int aCol4 = (tid & 7) << 2;
    const int bRow0 = tid >> 5;
    const int bCol4 = (tid & 31) << 2;

    for (int k0 = 0; k0 < K; k0 += 32) {
#pragma unroll
        for (int i = 0; i < 4; i++) {
            int r = aRow0 + i * 32;
            int gr = rowBase + r;
            if (gr >= M) gr = M - 1;
            float4 v = *(const float4*)(A + (size_t)gr * K + k0 + aCol4);
            As[r][aCol4 + 0] = v.x;
            As[r][aCol4 + 1] = v.y;
            As[r][aCol4 + 2] = v.z;
            As[r][aCol4 + 3] = v.w;
        }
#pragma unroll
        for (int i = 0; i < 4; i++) {
            int r = bRow0 + i * 8;
            float4 v = *(const float4*)(B + (size_t)(k0 + r) * N + colBase + bCol4);
            Bs[r][bCol4 + 0] = v.x;
            Bs[r][bCol4 + 1] = v.y;
            Bs[r][bCol4 + 2] = v.z;
            Bs[r][bCol4 + 3] = v.w;
        }
        __syncthreads();

#pragma unroll
        for (int kk = 0; kk < 4; kk++) {
            const int kb = kk * 8;
            float bhi[4][2], blo[4][2];
#pragma unroll
            for (int nt = 0; nt < 4; nt++) {
                int c = warpN * 32 + nt * 8 + lq;
                float b0 = Bs[kb + lr][c];
                float b1 = Bs[kb + lr + 4][c];
                bhi[nt][0] = to_tf32(b0);
                blo[nt][0] = to_tf32(b0 - bhi[nt][0]);
                bhi[nt][1] = to_tf32(b1);
                blo[nt][1] = to_tf32(b1 - bhi[nt][1]);
            }
#pragma unroll
            for (int mt = 0; mt < 4; mt++) {
                int r = warpM * 64 + mt * 16 + lq;
                float a0 = As[r][kb + lr];
                float a1 = As[r + 8][kb + lr];
                float a2 = As[r][kb + lr + 4];
                float a3 = As[r + 8][kb + lr + 4];
                float ah0 = to_tf32(a0), al0 = to_tf32(a0 - ah0);
                float ah1 = to_tf32(a1), al1 = to_tf32(a1 - ah1);
                float ah2 = to_tf32(a2), al2 = to_tf32(a2 - ah2);
                float ah3 = to_tf32(a3), al3 = to_tf32(a3 - ah3);
#pragma unroll
                for (int nt = 0; nt < 4; nt++) {
                    MMA_TF32(acc[mt][nt], al0, al1, al2, al3, bhi[nt][0], bhi[nt][1]);
                    MMA_TF32(acc[mt][nt], ah0, ah1, ah2, ah3, blo[nt][0], blo[nt][1]);
                    MMA_TF32(acc[mt][nt], ah0, ah1, ah2, ah3, bhi[nt][0], bhi[nt][1]);
                }
            }
        }
        __syncthreads();
    }

#pragma unroll
    for (int mt = 0; mt < 4; mt++) {
        int r0 = rowBase + warpM * 64 + mt * 16 + lq;
#pragma unroll
        for (int nt = 0; nt < 4; nt++) {
            int c = colBase + warpN * 32 + nt * 8 + lr * 2;
            float b0 = bias ? bias[c] : 0.f;
            float b1 = bias ? bias[c + 1] : 0.f;
            if (r0 < M) {
                float v0 = acc[mt][nt][0] + b0;
                float v1 = acc[mt][nt][1] + b1;
                if (act) { v0 = fmaxf(v0, 0.f); v1 = fmaxf(v1, 0.f); }
                *(float2*)(C + (size_t)r0 * N + c) = make_float2(v0, v1);
            }
            if (r0 + 8 < M) {
                float v2 = acc[mt][nt][2] + b0;
                float v3 = acc[mt][nt][3] + b1;
                if (act) { v2 = fmaxf(v2, 0.f); v3 = fmaxf(v3, 0.f); }
                *(float2*)(C + (size_t)(r0 + 8) * N + c) = make_float2(v2, v3);
            }
        }
    }
}

// ---------------- per-node attention scalars ----------------
__global__ void k_es_ed(const float* __restrict__ a_src, const float* __restrict__ a_dst) {
    int n = blockIdx.x * (blockDim.x >> 5) + (threadIdx.x >> 5);
    int lane = threadIdx.x & 31;
    if (n >= NN) return;
    float4 hv = *(const float4*)(g_h + (size_t)n * DF + lane * 4);
    float4 as = *(const float4*)(a_src + lane * 4);
    float4 ad = *(const float4*)(a_dst + lane * 4);
    float s = hv.x * as.x + hv.y * as.y + hv.z * as.z + hv.w * as.w;
    float d = hv.x * ad.x + hv.y * ad.y + hv.z * ad.z + hv.w * ad.w;
#pragma unroll
    for (int o = 16; o > 0; o >>= 1) {
        s += __shfl_xor_sync(0xffffffff, s, o);
        d += __shfl_xor_sync(0xffffffff, d, o);
    }
    if (lane == 0) {
        g_es[n] = s;
        g_ed[n] = d;
    }
}

// ---------------- fused per-node softmax + aggregation (warp per node) ----------------
__global__ void k_node_aggr(const float* __restrict__ bias) {
    int n = blockIdx.x * (blockDim.x >> 5) + (threadIdx.x >> 5);
    int lane = threadIdx.x & 31;
    if (n >= NN) return;
    int r0 = g_rowstart[n];
    int r1 = g_rowstart[n + 1];
    float edn = g_ed[n];

    // pass 1: segment max
    float m = -1e30f;
    for (int i = r0 + lane; i < r1; i += 32)
        m = fmaxf(m, leaky(g_es[g_csr[i]] + edn));
#pragma unroll
    for (int o = 16; o > 0; o >>= 1)
        m = fmaxf(m, __shfl_xor_sync(0xffffffff, m, o));

    // pass 2: segment sum of exp
    float s = 0.f;
    for (int i = r0 + lane; i < r1; i += 32)
        s += expf(leaky(g_es[g_csr[i]] + edn) - m);
#pragma unroll
    for (int o = 16; o > 0; o >>= 1)
        s += __shfl_xor_sync(0xffffffff, s, o);
    float inv = 1.f / s;

    // pass 3: weighted gather (whole warp per edge; each lane holds 4 columns)
    float4 acc = make_float4(0.f, 0.f, 0.f, 0.f);
    for (int i = r0; i < r1; i++) {
        int src = g_csr[i];
        float w = expf(leaky(g_es[src] + edn) - m) * inv;
        float4 hv = *(const float4*)(g_h + (size_t)src * DF + lane * 4);
        acc.x += w * hv.x;
        acc.y += w * hv.y;
        acc.z += w * hv.z;
        acc.w += w * hv.w;
    }
    float4 bv = *(const float4*)(bias + lane * 4);
    float4 r;
    r.x = leaky(acc.x + bv.x);
    r.y = leaky(acc.y + bv.y);
    r.z = leaky(acc.z + bv.z);
    r.w = leaky(acc.w + bv.w);
    *(float4*)(g_x + (size_t)n * DF + lane * 4) = r;
}

// ---------------- output head ----------------
__global__ void k_out(const float* __restrict__ Y, const float* __restrict__ Wout,
                      const float* __restrict__ bout, float* __restrict__ out) {
    int n = blockIdx.x * (blockDim.x >> 5) + (threadIdx.x >> 5);
    int lane = threadIdx.x & 31;
    if (n >= NN) return;
    float acc0 = 0.f, acc1 = 0.f, acc2 = 0.f, acc3 = 0.f;
    const float* y = Y + (size_t)n * DLIN;
    for (int k = lane; k < DLIN; k += 32) {
        float v = y[k];
        const float4 wv = *(const float4*)(Wout + k * 4);
        acc0 += v * wv.x;
        acc1 += v * wv.y;
        acc2 += v * wv.z;
        acc3 += v * wv.w;
    }
#pragma unroll
    for (int o = 16; o > 0; o >>= 1) {
        acc0 += __shfl_xor_sync(0xffffffff, acc0, o);
        acc1 += __shfl_xor_sync(0xffffffff, acc1, o);
        acc2 += __shfl_xor_sync(0xffffffff, acc2, o);
        acc3 += __shfl_xor_sync(0xffffffff, acc3, o);
    }
    if (lane == 0) {
        float4 r;
        r.x = acc0 + bout[0];
        r.y = acc1 + bout[1];
        r.z = acc2 + bout[2];
        r.w = acc3 + bout[3];
        *(float4*)(out + (size_t)n * 4) = r;
    }
}

extern "C" void kernel_launch(void* const* d_in, const int* in_sizes, int n_in,
                              void* d_out, int out_size) {
    const float *x, *conv_W, *conv_as, *conv_ad, *conv_b;
    const float *lin_W0, *lin_b0, *lin_W1, *lin_b1, *lin_W2, *lin_b2, *lin_Wout, *lin_bout;
    const void* ei;

    if (in_sizes[0] == NN * DF) {
        x        = (const float*)d_in[0];
        ei       = d_in[1];
        conv_W   = (const float*)d_in[2];
        conv_as  = (const float*)d_in[3];
        conv_ad  = (const float*)d_in[4];
        conv_b   = (const float*)d_in[5];
        lin_W0   = (const float*)d_in[6];
        lin_b0   = (const float*)d_in[7];
        lin_W1   = (const float*)d_in[8];
        lin_b1   = (const float*)d_in[9];
        lin_W2   = (const float*)d_in[10];
        lin_b2   = (const float*)d_in[11];
        lin_Wout = (const float*)d_in[12];
        lin_bout = (const float*)d_in[13];
    } else {
        conv_W   = (const float*)d_in[0];
        conv_ad  = (const float*)d_in[1];
        conv_as  = (const float*)d_in[2];
        conv_b   = (const float*)d_in[3];
        ei       = d_in[4];
        lin_W0   = (const float*)d_in[5];
        lin_W1   = (const float*)d_in[6];
        lin_W2   = (const float*)d_in[7];
        lin_Wout = (const float*)d_in[8];
        lin_b0   = (const float*)d_in[9];
        lin_b1   = (const float*)d_in[10];
        lin_b2   = (const float*)d_in[11];
        lin_bout = (const float*)d_in[12];
        x        = (const float*)d_in[13];
    }
    float* out = (float*)d_out;

    void *p_x, *p_h, *p_y0, *p_y1;
    cudaGetSymbolAddress(&p_x, g_x);
    cudaGetSymbolAddress(&p_h, g_h);
    cudaGetSymbolAddress(&p_y0, g_y0);
    cudaGetSymbolAddress(&p_y1, g_y1);

    // edges + CSR (once per launch)
    k_detect_dtype<<<1, 32>>>((const int*)ei);
    k_build_edges<<<(NEL + 255) / 256, 256>>>(ei);
    k_zero_deg<<<(NN + 255) / 256, 256>>>();
    k_hist<<<(NEL + 255) / 256, 256>>>();
    k_scan1<<<NBLK, 1024>>>();
    k_scan2<<<1, 32>>>();
    k_scan3<<<(NN + 255) / 256, 256>>>();
    k_scatter<<<(NEL + 255) / 256, 256>>>();

    dim3 grid128(1, (NN + 127) / 128);
    dim3 grid512(DLIN / 128, (NN + 127) / 128);
    const int wpb = 8;   // warps per block for warp-per-node kernels
    const int nodeBlocks = (NN + wpb - 1) / wpb;

    const float* curX = x;
    for (int layer = 0; layer < 3; layer++) {
        const float* W  = conv_W + (size_t)layer * DF * DF;
        const float* as = conv_as + (size_t)layer * DF;
        const float* ad = conv_ad + (size_t)layer * DF;
        const float* b  = conv_b + (size_t)layer * DF;

        k_mma<<<grid128, 256>>>(curX, W, nullptr, (float*)p_h, NN, DF, DF, 0);
        k_es_ed<<<nodeBlocks, wpb * 32>>>(as, ad);
        k_node_aggr<<<nodeBlocks, wpb * 32>>>(b);
        curX = (const float*)p_x;
    }

    k_mma<<<grid512, 256>>>((const float*)p_x, lin_W0, lin_b0, (float*)p_y0, NN, DLIN, DF, 1);
    k_mma<<<grid512, 256>>>((const float*)p_y0, lin_W1, lin_b1, (float*)p_y1, NN, DLIN, DLIN, 1);
    k_mma<<<grid512, 256>>>((const float*)p_y1, lin_W2, lin_b2, (float*)p_y0, NN, DLIN, DLIN, 1);
    k_out<<<nodeBlocks, wpb * 32>>>((const float*)p_y0, lin_Wout, lin_bout, out);
}